// round 15
// baseline (speedup 1.0000x reference)
#include <cuda_runtime.h>
#include <cuda_bf16.h>
#include <cuda_fp16.h>
#include <mma.h>
#include <cstdint>

using namespace nvcuda;

#define NN 50000
#define NP 50048          // 782 * 64
#define NE 800000
#define ET 850000         // NE + NN self loops
#define NS 0.2f
#define NBLK 196          // ceil(NN/256)
#define NCUT 25024        // gather1/gemm2 pipeline split (391 * 64)

// ---------------- scratch (device globals) -----------------------------------
__device__ __half g_h1h[NN * 128];
__device__ __half g_o1h[NN * 128];   // relu(out1) split hi
__device__ __half g_o1l[NN * 128];   // relu(out1) split lo
__device__ float  g_as1[NN * 4];
__device__ float  g_ad1[NN * 4];
__device__ __half g_h2h[NN * 64];
__device__ float  g_as2[NN];
__device__ float  g_ad2[NN];
__device__ float  g_mx1[4];
__device__ float  g_mx2;
__device__ int g_deg[NN];            // invariant: zero before/after every call
__device__ int g_off[NN + 1];
__device__ int g_cur[NN];
__device__ int g_srcidx[ET];
__device__ unsigned int g_blkst[NBLK];
__device__ __half g_w1[128 * 144];
__device__ __half g_w2[128 * 80];

__device__ __forceinline__ float lrelu(float v) { return v >= 0.f ? v : NS * v; }

__device__ __forceinline__ void atomicMaxF(float* addr, float v) {
    if (v >= 0.f) atomicMax((int*)addr, __float_as_int(v));
    else          atomicMin((unsigned int*)addr, __float_as_uint(v));
}

__device__ __forceinline__ uint32_t smem_u32(const void* p) {
    uint32_t a;
    asm("{ .reg .u64 t; cvta.to.shared.u64 t, %1; cvt.u32.u64 %0, t; }" : "=r"(a) : "l"(p));
    return a;
}
__device__ __forceinline__ void cp16(void* smem, const void* gmem) {
    asm volatile("cp.async.cg.shared.global [%0], [%1], 16;"
                 :: "r"(smem_u32(smem)), "l"(gmem) : "memory");
}
__device__ __forceinline__ void cp_commit_wait() {
    asm volatile("cp.async.commit_group;" ::: "memory");
    asm volatile("cp.async.wait_group 0;" ::: "memory");
}

// ---------------- hist: 8 edges/thread, batched atomics ------------------------
__global__ void k_hist(const int* __restrict__ ei) {
    int i = blockIdx.x * blockDim.x + threadIdx.x;
    if (i >= NE / 8) return;
    int4 a = ((const int4*)(ei + NE))[2 * i];
    int4 b = ((const int4*)(ei + NE))[2 * i + 1];
    atomicAdd(&g_deg[a.x], 1); atomicAdd(&g_deg[a.y], 1);
    atomicAdd(&g_deg[a.z], 1); atomicAdd(&g_deg[a.w], 1);
    atomicAdd(&g_deg[b.x], 1); atomicAdd(&g_deg[b.y], 1);
    atomicAdd(&g_deg[b.z], 1); atomicAdd(&g_deg[b.w], 1);
}

// ---------------- convw + reset (main stream) ---------------------------------
#define CONV_BLKS 112
__global__ void k_convw(const float* __restrict__ W1, const float* __restrict__ W2,
                        const float* __restrict__ as1, const float* __restrict__ ad1,
                        const float* __restrict__ as2, const float* __restrict__ ad2) {
    int b = blockIdx.x, t = threadIdx.x;
    if (b == CONV_BLKS) {
        if (t < NBLK) g_blkst[t] = 0u;
        if (t == 0) {
            g_off[NN] = ET;
            g_mx1[0] = -3.4e38f; g_mx1[1] = -3.4e38f;
            g_mx1[2] = -3.4e38f; g_mx1[3] = -3.4e38f;
            g_mx2 = -3.4e38f;
        }
        return;
    }
    int s = b * 256 + t;
    float val; int dsth, dstl;
    if (s < 16384) {
        int k = s >> 7, n = s & 127;
        val = W1[k * 128 + n];
        dsth = k * 144 + n; dstl = 1;
    } else if (s < 17408) {
        int i = s - 16384;
        int k = i >> 3, c = i & 7, h = c >> 1;
        const float* a = (c & 1) ? ad1 : as1;
        float sum = 0.f;
#pragma unroll
        for (int f = 0; f < 32; f++) sum += W1[k * 128 + h * 32 + f] * a[h * 32 + f];
        val = sum; dsth = k * 144 + 128 + c; dstl = 1;
    } else if (s < 18432) {
        int i = s - 17408;
        int k = i >> 3, c = i & 7;
        val = 0.f; dsth = k * 144 + 136 + c; dstl = 1;
    } else if (s < 26624) {
        int i = s - 18432;
        int k = i >> 6, n = i & 63;
        val = W2[k * 64 + n];
        dsth = k * 80 + n; dstl = 2;
    } else if (s < 26880) {
        int i = s - 26624;
        int k = i >> 1, c = i & 1;
        const float* a = c ? ad2 : as2;
        float sum = 0.f;
#pragma unroll
        for (int f = 0; f < 64; f++) sum += W2[k * 64 + f] * a[f];
        val = sum; dsth = k * 80 + 64 + c; dstl = 2;
    } else if (s < 28672) {
        int i = s - 26880;
        int k = i / 14, c = i % 14;
        val = 0.f; dsth = k * 80 + 66 + c; dstl = 2;
    } else return;
    __half hv = __float2half_rn(val);
    if (dstl == 1) g_w1[dsth] = hv;
    else           g_w2[dsth] = hv;
}

// ---------------- single-pass scan with decoupled lookback --------------------
__global__ void k_scan() {
    __shared__ int sh[256];
    __shared__ int s_excl;
    int t = threadIdx.x, b = blockIdx.x;
    int i = b * 256 + t;
    int v = (i < NN) ? g_deg[i] + 1 : 0;
    sh[t] = v;
    __syncthreads();
#pragma unroll
    for (int o = 1; o < 256; o <<= 1) {
        int tv = (t >= o) ? sh[t - o] : 0;
        __syncthreads();
        sh[t] += tv;
        __syncthreads();
    }
    int incl = sh[t];
    int total = sh[255];

    if (t == 0) {
        if (b == 0) {
            atomicExch(&g_blkst[0], ((unsigned)total << 2) | 2u);
            s_excl = 0;
        } else {
            atomicExch(&g_blkst[b], ((unsigned)total << 2) | 1u);
            int run = 0;
            for (int p = b - 1; p >= 0; p--) {
                unsigned st;
                do { st = atomicAdd(&g_blkst[p], 0u); } while ((st & 3u) == 0u);
                run += (int)(st >> 2);
                if ((st & 3u) == 2u) break;
            }
            s_excl = run;
            atomicExch(&g_blkst[b], ((unsigned)(run + total) << 2) | 2u);
        }
    }
    __syncthreads();
    if (i < NN) {
        int off = s_excl + incl - v;
        g_off[i] = off;
        g_srcidx[off] = i;
        g_cur[i] = off + 1;
        g_deg[i] = 0;
    }
}

// ---------------- fill: 8 edges/thread, atomics batched before stores ----------
__global__ void k_fill(const int* __restrict__ ei) {
    int i = blockIdx.x * blockDim.x + threadIdx.x;
    if (i >= NE / 8) return;
    int4 sa = ((const int4*)ei)[2 * i];
    int4 sb = ((const int4*)ei)[2 * i + 1];
    int4 da = ((const int4*)(ei + NE))[2 * i];
    int4 db = ((const int4*)(ei + NE))[2 * i + 1];
    int p0 = atomicAdd(&g_cur[da.x], 1);
    int p1 = atomicAdd(&g_cur[da.y], 1);
    int p2 = atomicAdd(&g_cur[da.z], 1);
    int p3 = atomicAdd(&g_cur[da.w], 1);
    int p4 = atomicAdd(&g_cur[db.x], 1);
    int p5 = atomicAdd(&g_cur[db.y], 1);
    int p6 = atomicAdd(&g_cur[db.z], 1);
    int p7 = atomicAdd(&g_cur[db.w], 1);
    g_srcidx[p0] = sa.x; g_srcidx[p1] = sa.y;
    g_srcidx[p2] = sa.z; g_srcidx[p3] = sa.w;
    g_srcidx[p4] = sb.x; g_srcidx[p5] = sb.y;
    g_srcidx[p6] = sb.z; g_srcidx[p7] = sb.w;
}

// ---------------- GEMM1: [h1 | as1 | ad1] = x @ [W1 | W1@P] -------------------
#define LDA 136
#define LDW1 152
#define ST1 148
__global__ __launch_bounds__(256)
void k_gemm1_mma(const float* __restrict__ X) {
    extern __shared__ char raw[];
    __half* sAh = (__half*)raw;
    __half* sAl = sAh + 64 * LDA;
    __half* sW  = (__half*)(raw + 4 * 64 * LDA);
    float*  sX  = (float*)sW;
    float* stage = (float*)raw;
    int tid = threadIdx.x;
    int row0 = blockIdx.x * 64;

#pragma unroll
    for (int ii = 0; ii < 8; ii++) {
        int i = tid + ii * 256;
        int r = i >> 5, c4 = i & 31;
        if (row0 + r < NN)
            cp16(sX + r * 128 + 4 * c4, (const float4*)X + (size_t)(row0 + r) * 32 + c4);
        else
            *(float4*)(sX + r * 128 + 4 * c4) = make_float4(0.f, 0.f, 0.f, 0.f);
    }
    cp_commit_wait();
    __syncthreads();
#pragma unroll
    for (int ii = 0; ii < 8; ii++) {
        int i = tid + ii * 256;
        int r = i >> 5, c4 = i & 31;
        float4 v = *(const float4*)(sX + r * 128 + 4 * c4);
        __half2 h0 = __floats2half2_rn(v.x, v.y);
        __half2 h1 = __floats2half2_rn(v.z, v.w);
        float2 f0 = __half22float2(h0), f1 = __half22float2(h1);
        __half2 l0 = __floats2half2_rn(v.x - f0.x, v.y - f0.y);
        __half2 l1 = __floats2half2_rn(v.z - f1.x, v.w - f1.y);
        uint2 uh, ul;
        uh.x = *(uint32_t*)&h0; uh.y = *(uint32_t*)&h1;
        ul.x = *(uint32_t*)&l0; ul.y = *(uint32_t*)&l1;
        *(uint2*)(sAh + r * LDA + 4 * c4) = uh;
        *(uint2*)(sAl + r * LDA + 4 * c4) = ul;
    }
    __syncthreads();
    for (int i = tid; i < 2304; i += 256) {
        int k = i / 18, j = i % 18;
        cp16(sW + k * LDW1 + 8 * j, (const uint4*)g_w1 + i);
    }
    cp_commit_wait();
    __syncthreads();

    int w = tid >> 5, wr = w >> 1, wc = w & 1;
    const int nf = wc ? 4 : 5;
    const int col0 = wc * 80;

    wmma::fragment<wmma::accumulator, 16, 16, 16, float> c[5];
#pragma unroll
    for (int j = 0; j < 5; j++) wmma::fill_fragment(c[j], 0.f);

    for (int kk = 0; kk < 128; kk += 16) {
        wmma::fragment<wmma::matrix_a, 16, 16, 16, __half, wmma::row_major> ah, al;
        wmma::load_matrix_sync(ah, sAh + (wr * 16) * LDA + kk, LDA);
        wmma::load_matrix_sync(al, sAl + (wr * 16) * LDA + kk, LDA);
#pragma unroll
        for (int j = 0; j < 5; j++) {
            if (j >= nf) break;
            wmma::fragment<wmma::matrix_b, 16, 16, 16, __half, wmma::row_major> bh;
            wmma::load_matrix_sync(bh, sW + kk * LDW1 + col0 + j * 16, LDW1);
            wmma::mma_sync(c[j], ah, bh, c[j]);
            wmma::mma_sync(c[j], al, bh, c[j]);
        }
    }
    __syncthreads();
#pragma unroll
    for (int j = 0; j < 5; j++) {
        if (j >= nf) break;
        wmma::store_matrix_sync(stage + (wr * 16) * ST1 + col0 + j * 16,
                                c[j], ST1, wmma::mem_row_major);
    }
    __syncthreads();

    {
        int r = tid >> 2, q = tid & 3;
        int row = row0 + r;
        if (row < NN) {
            const float* sp = stage + r * ST1 + 32 * q;
            uint4* dp = (uint4*)(g_h1h + (size_t)row * 128 + 32 * q);
#pragma unroll
            for (int u = 0; u < 4; u++) {
                float4 a = *(const float4*)(sp + 8 * u);
                float4 b = *(const float4*)(sp + 8 * u + 4);
                __half2 h0 = __floats2half2_rn(a.x, a.y);
                __half2 h1 = __floats2half2_rn(a.z, a.w);
                __half2 h2 = __floats2half2_rn(b.x, b.y);
                __half2 h3 = __floats2half2_rn(b.z, b.w);
                uint4 uu;
                uu.x = *(uint32_t*)&h0; uu.y = *(uint32_t*)&h1;
                uu.z = *(uint32_t*)&h2; uu.w = *(uint32_t*)&h3;
                dp[u] = uu;
            }
        }
    }
    if (tid < 64) {
        int row = row0 + tid;
        const float* sp = stage + tid * ST1 + 128;
        float ps[4];
#pragma unroll
        for (int h = 0; h < 4; h++) {
            float a_ = sp[2 * h], d_ = sp[2 * h + 1];
            if (row < NN) {
                g_as1[row * 4 + h] = a_;
                g_ad1[row * 4 + h] = d_;
                ps[h] = a_;
            } else ps[h] = -3.4e38f;
        }
#pragma unroll
        for (int h = 0; h < 4; h++) {
#pragma unroll
            for (int o = 16; o >= 1; o >>= 1)
                ps[h] = fmaxf(ps[h], __shfl_xor_sync(0xffffffffu, ps[h], o));
        }
        if ((tid & 31) == 0) {
#pragma unroll
            for (int h = 0; h < 4; h++) atomicMaxF(&g_mx1[h], ps[h]);
        }
    }
}

// ---------------- GEMM2 (block-offset for pipeline split) ---------------------
#define LDW2 88
#define ST2 84
__global__ __launch_bounds__(256)
void k_gemm2_mma(int blk0) {
    extern __shared__ char raw[];
    __half* sAh = (__half*)raw;
    __half* sAl = sAh + 64 * LDA;
    __half* sW  = (__half*)(raw + 4 * 64 * LDA);
    float* stage = (float*)raw;
    int tid = threadIdx.x;
    int row0 = (blockIdx.x + blk0) * 64;

#pragma unroll
    for (int ii = 0; ii < 4; ii++) {
        int i = tid + ii * 256;
        int r = i >> 4, c = i & 15;
        if (row0 + r < NN) {
            cp16(sAh + r * LDA + 8 * c, (const uint4*)g_o1h + (size_t)(row0 + r) * 16 + c);
            cp16(sAl + r * LDA + 8 * c, (const uint4*)g_o1l + (size_t)(row0 + r) * 16 + c);
        } else {
            *(uint4*)(sAh + r * LDA + 8 * c) = make_uint4(0, 0, 0, 0);
            *(uint4*)(sAl + r * LDA + 8 * c) = make_uint4(0, 0, 0, 0);
        }
    }
    for (int i = tid; i < 1280; i += 256) {
        int k = i / 10, j = i % 10;
        cp16(sW + k * LDW2 + 8 * j, (const uint4*)g_w2 + i);
    }
    cp_commit_wait();
    __syncthreads();

    int w = tid >> 5, wr = w >> 1, wc = w & 1;
    const int nf = wc ? 2 : 3;
    const int col0 = wc * 48;

    wmma::fragment<wmma::accumulator, 16, 16, 16, float> c[3];
#pragma unroll
    for (int j = 0; j < 3; j++) wmma::fill_fragment(c[j], 0.f);

    for (int kk = 0; kk < 128; kk += 16) {
        wmma::fragment<wmma::matrix_a, 16, 16, 16, __half, wmma::row_major> ah, al;
        wmma::load_matrix_sync(ah, sAh + (wr * 16) * LDA + kk, LDA);
        wmma::load_matrix_sync(al, sAl + (wr * 16) * LDA + kk, LDA);
#pragma unroll
        for (int j = 0; j < 3; j++) {
            if (j >= nf) break;
            wmma::fragment<wmma::matrix_b, 16, 16, 16, __half, wmma::row_major> bh;
            wmma::load_matrix_sync(bh, sW + kk * LDW2 + col0 + j * 16, LDW2);
            wmma::mma_sync(c[j], ah, bh, c[j]);
            wmma::mma_sync(c[j], al, bh, c[j]);
        }
    }
    __syncthreads();
#pragma unroll
    for (int j = 0; j < 3; j++) {
        if (j >= nf) break;
        wmma::store_matrix_sync(stage + (wr * 16) * ST2 + col0 + j * 16,
                                c[j], ST2, wmma::mem_row_major);
    }
    __syncthreads();

    {
        int r = tid >> 2, q = tid & 3;
        int row = row0 + r;
        if (row < NN) {
            const float* sp = stage + r * ST2 + 16 * q;
            uint4* dp = (uint4*)(g_h2h + (size_t)row * 64 + 16 * q);
#pragma unroll
            for (int u = 0; u < 2; u++) {
                float4 a = *(const float4*)(sp + 8 * u);
                float4 b = *(const float4*)(sp + 8 * u + 4);
                __half2 h0 = __floats2half2_rn(a.x, a.y);
                __half2 h1 = __floats2half2_rn(a.z, a.w);
                __half2 h2 = __floats2half2_rn(b.x, b.y);
                __half2 h3 = __floats2half2_rn(b.z, b.w);
                uint4 uu;
                uu.x = *(uint32_t*)&h0; uu.y = *(uint32_t*)&h1;
                uu.z = *(uint32_t*)&h2; uu.w = *(uint32_t*)&h3;
                dp[u] = uu;
            }
        }
    }
    if (tid < 64) {
        int row = row0 + tid;
        float ps;
        if (row < NN) {
            ps = stage[tid * ST2 + 64];
            g_as2[row] = ps;
            g_ad2[row] = stage[tid * ST2 + 65];
        } else ps = -3.4e38f;
#pragma unroll
        for (int o = 16; o >= 1; o >>= 1)
            ps = fmaxf(ps, __shfl_xor_sync(0xffffffffu, ps, o));
        if ((tid & 31) == 0) atomicMaxF(&g_mx2, ps);
    }
}

// ---------------- gather1 (node-offset for pipeline split) --------------------
__global__ __launch_bounds__(256)
void k_gather1(const float* __restrict__ b1, int n0, int n1) {
    int n = n0 + blockIdx.x * 8 + (threadIdx.x >> 5);
    if (n >= n1) return;
    int lane = threadIdx.x & 31;
    int g = lane >> 4, li = lane & 15;
    int head = li >> 2;
    float adh = g_ad1[4 * n + head];
    int beg = g_off[n], end = g_off[n + 1];

    float mh = lrelu(g_mx1[head] + adh);

    float acc[8];
#pragma unroll
    for (int q = 0; q < 8; q++) acc[q] = 0.f;
    float den = 0.f;

    int j0 = beg + g;
    float aA = 0.f, aB = 0.f;
    uint4 uA = make_uint4(0, 0, 0, 0), uB = make_uint4(0, 0, 0, 0);
    if (j0 < end) {
        int s = g_srcidx[j0];
        aA = g_as1[4 * s + head];
        uA = *(const uint4*)(g_h1h + (size_t)s * 128 + 8 * li);
    }
    if (j0 + 2 < end) {
        int s = g_srcidx[j0 + 2];
        aB = g_as1[4 * s + head];
        uB = *(const uint4*)(g_h1h + (size_t)s * 128 + 8 * li);
    }
    for (int j = j0; j < end; j += 2) {
        float aC = 0.f; uint4 uC = make_uint4(0, 0, 0, 0);
        if (j + 4 < end) {
            int s = g_srcidx[j + 4];
            aC = g_as1[4 * s + head];
            uC = *(const uint4*)(g_h1h + (size_t)s * 128 + 8 * li);
        }
        float w = __expf(lrelu(aA + adh) - mh);
        den += w;
        const __half2* hp = (const __half2*)&uA;
#pragma unroll
        for (int q = 0; q < 4; q++) {
            float2 f = __half22float2(hp[q]);
            acc[2 * q] += w * f.x;
            acc[2 * q + 1] += w * f.y;
        }
        aA = aB; uA = uB;
        aB = aC; uB = uC;
    }
    den += __shfl_xor_sync(0xffffffffu, den, 16);
#pragma unroll
    for (int q = 0; q < 8; q++) acc[q] += __shfl_xor_sync(0xffffffffu, acc[q], 16);

    if (g == 0) {
        float inv = 1.f / (den + 1e-16f);
        float4 b0 = *(const float4*)(b1 + 8 * li);
        float4 b4 = *(const float4*)(b1 + 8 * li + 4);
        float v[8];
        v[0] = fmaxf(acc[0] * inv + b0.x, 0.f); v[1] = fmaxf(acc[1] * inv + b0.y, 0.f);
        v[2] = fmaxf(acc[2] * inv + b0.z, 0.f); v[3] = fmaxf(acc[3] * inv + b0.w, 0.f);
        v[4] = fmaxf(acc[4] * inv + b4.x, 0.f); v[5] = fmaxf(acc[5] * inv + b4.y, 0.f);
        v[6] = fmaxf(acc[6] * inv + b4.z, 0.f); v[7] = fmaxf(acc[7] * inv + b4.w, 0.f);
        uint4 uh, ul;
        uint32_t* uhp = (uint32_t*)&uh;
        uint32_t* ulp = (uint32_t*)&ul;
#pragma unroll
        for (int q = 0; q < 4; q++) {
            __half2 h = __floats2half2_rn(v[2 * q], v[2 * q + 1]);
            float2 f = __half22float2(h);
            __half2 l = __floats2half2_rn(v[2 * q] - f.x, v[2 * q + 1] - f.y);
            uhp[q] = *(uint32_t*)&h;
            ulp[q] = *(uint32_t*)&l;
        }
        *(uint4*)(g_o1h + (size_t)n * 128 + 8 * li) = uh;
        *(uint4*)(g_o1l + (size_t)n * 128 + 8 * li) = ul;
    }
}

// ---------------- gather2: 4 edges/warp, depth-2 pipeline ---------------------
__global__ __launch_bounds__(256)
void k_gather2(const float* __restrict__ b2, float* __restrict__ out) {
    int n = blockIdx.x * 8 + (threadIdx.x >> 5);
    if (n >= NN) return;
    int lane = threadIdx.x & 31;
    int g = lane >> 3, li = lane & 7;
    float adh = g_ad2[n];
    int beg = g_off[n], end = g_off[n + 1];

    float mh = lrelu(g_mx2 + adh);

    float acc[8];
#pragma unroll
    for (int q = 0; q < 8; q++) acc[q] = 0.f;
    float den = 0.f;

    int j0 = beg + g;
    float aA = 0.f, aB = 0.f;
    uint4 uA = make_uint4(0, 0, 0, 0), uB = make_uint4(0, 0, 0, 0);
    if (j0 < end) {
        int s = g_srcidx[j0];
        aA = g_as2[s];
        uA = *(const uint4*)(g_h2h + (size_t)s * 64 + 8 * li);
    }
    if (j0 + 4 < end) {
        int s = g_srcidx[j0 + 4];
        aB = g_as2[s];
        uB = *(const uint4*)(g_h2h + (size_t)s * 64 + 8 * li);
    }
    for (int j = j0; j < end; j += 4) {
        float aC = 0.f; uint4 uC = make_uint4(0, 0, 0, 0);
        if (j + 8 < end) {
            int s = g_srcidx[j + 8];
            aC = g_as2[s];
            uC = *(const uint4*)(g_h2h + (size_t)s * 64 + 8 * li);
        }
        float w = __expf(lrelu(aA + adh) - mh);
        den += w;
        const __half2* hp = (const __half2*)&uA;
#pragma unroll
        for (int q = 0; q < 4; q++) {
            float2 f = __half22float2(hp[q]);
            acc[2 * q] += w * f.x;
            acc[2 * q + 1] += w * f.y;
        }
        aA = aB; uA = uB;
        aB = aC; uB = uC;
    }
    den += __shfl_xor_sync(0xffffffffu, den, 8);
    den += __shfl_xor_sync(0xffffffffu, den, 16);
#pragma unroll
    for (int q = 0; q < 8; q++) {
        acc[q] += __shfl_xor_sync(0xffffffffu, acc[q], 8);
        acc[q] += __shfl_xor_sync(0xffffffffu, acc[q], 16);
    }

    if (g == 0) {
        float inv = 1.f / (den + 1e-16f);
        float4 b0 = *(const float4*)(b2 + 8 * li);
        float4 b4 = *(const float4*)(b2 + 8 * li + 4);
        float* op = out + (size_t)n * 64 + 8 * li;
        *(float4*)op = make_float4(acc[0] * inv + b0.x, acc[1] * inv + b0.y,
                                   acc[2] * inv + b0.z, acc[3] * inv + b0.w);
        *(float4*)(op + 4) = make_float4(acc[4] * inv + b4.x, acc[5] * inv + b4.y,
                                         acc[6] * inv + b4.z, acc[7] * inv + b4.w);
    }
}

// ---------------- launch ------------------------------------------------------
extern "C" void kernel_launch(void* const* d_in, const int* in_sizes, int n_in,
                              void* d_out, int out_size) {
    const float* x   = (const float*)d_in[0];
    const int*   ei  = (const int*)d_in[1];
    const float* W1  = (const float*)d_in[2];
    const float* as1 = (const float*)d_in[3];
    const float* ad1 = (const float*)d_in[4];
    const float* b1  = (const float*)d_in[5];
    const float* W2  = (const float*)d_in[6];
    const float* as2 = (const float*)d_in[7];
    const float* ad2 = (const float*)d_in[8];
    const float* b2  = (const float*)d_in[9];
    float* out = (float*)d_out;

    const int smem1 = 4 * 64 * LDA + 2 * 128 * LDW1;   // 73728
    const int smem2 = 4 * 64 * LDA + 2 * 128 * LDW2;   // 57344
    static cudaStream_t s_side = nullptr;
    static cudaEvent_t ev0 = nullptr, evC = nullptr, evS = nullptr;
    static cudaEvent_t evG1a = nullptr, evG1b = nullptr, evM2 = nullptr;
    if (!s_side) {
        cudaFuncSetAttribute(k_gemm1_mma, cudaFuncAttributeMaxDynamicSharedMemorySize, smem1);
        cudaFuncSetAttribute(k_gemm2_mma, cudaFuncAttributeMaxDynamicSharedMemorySize, smem2);
        cudaStreamCreateWithFlags(&s_side, cudaStreamNonBlocking);
        cudaEventCreateWithFlags(&ev0, cudaEventDisableTiming);
        cudaEventCreateWithFlags(&evC, cudaEventDisableTiming);
        cudaEventCreateWithFlags(&evS, cudaEventDisableTiming);
        cudaEventCreateWithFlags(&evG1a, cudaEventDisableTiming);
        cudaEventCreateWithFlags(&evG1b, cudaEventDisableTiming);
        cudaEventCreateWithFlags(&evM2, cudaEventDisableTiming);
    }

    // fork at t=0: hist on side (needs only ei)
    cudaEventRecord(ev0, 0);
    cudaStreamWaitEvent(s_side, ev0, 0);
    k_hist<<<(NE / 8 + 255) / 256, 256, 0, s_side>>>(ei);

    // main: convw + reset
    k_convw<<<CONV_BLKS + 1, 256>>>(W1, W2, as1, ad1, as2, ad2);
    cudaEventRecord(evC, 0);

    // side: scan (hist + reset), fill
    cudaStreamWaitEvent(s_side, evC, 0);
    k_scan<<<NBLK, 256, 0, s_side>>>();
    k_fill<<<(NE / 8 + 255) / 256, 256, 0, s_side>>>(ei);
    cudaEventRecord(evS, s_side);

    // main: gemm1 concurrent with side CSR chain
    k_gemm1_mma<<<NP / 64, 256, smem1>>>(x);

    // join + gather1/gemm2 pipeline:
    //   main: gather1A (nodes < NCUT), gather1B (rest)
    //   side: gemm2a (tiles < NCUT) after gather1A; gemm2b after gather1B
    cudaStreamWaitEvent(0, evS, 0);
    k_gather1<<<NCUT / 8, 256>>>(b1, 0, NCUT);
    cudaEventRecord(evG1a, 0);
    k_gather1<<<(NN - NCUT + 7) / 8, 256>>>(b1, NCUT, NN);
    cudaEventRecord(evG1b, 0);

    cudaStreamWaitEvent(s_side, evG1a, 0);
    k_gemm2_mma<<<NCUT / 64, 256, smem2, s_side>>>(0);
    cudaStreamWaitEvent(s_side, evG1b, 0);
    k_gemm2_mma<<<NP / 64 - NCUT / 64, 256, smem2, s_side>>>(NCUT / 64);
    cudaEventRecord(evM2, s_side);

    // final: gather2 needs all of gemm2
    cudaStreamWaitEvent(0, evM2, 0);
    k_gather2<<<(NN + 7) / 8, 256>>>(b2, out);
}

// round 16
// speedup vs baseline: 1.0486x; 1.0486x over previous
#include <cuda_runtime.h>
#include <cuda_bf16.h>
#include <cuda_fp16.h>
#include <mma.h>
#include <cstdint>

using namespace nvcuda;

#define NN 50000
#define NP 50048          // 782 * 64
#define NE 800000
#define ET 850000         // NE + NN self loops
#define NS 0.2f
#define NBLK 196          // ceil(NN/256)

// ---------------- scratch (device globals) -----------------------------------
__device__ __half g_h1h[NN * 128];
__device__ __half g_o1h[NN * 128];   // relu(out1) split hi
__device__ __half g_o1l[NN * 128];   // relu(out1) split lo
__device__ float  g_as1[NN * 4];
__device__ float  g_ad1[NN * 4];
__device__ __half g_h2h[NN * 64];
__device__ float  g_as2[NN];
__device__ float  g_ad2[NN];
__device__ float  g_mx1[4];
__device__ float  g_mx2;
__device__ int g_deg[NN];            // invariant: zero before/after every call
__device__ int g_off[NN + 1];
__device__ int g_cur[NN];
__device__ int g_srcidx[ET];
__device__ unsigned int g_blkst[NBLK];
__device__ __half g_w1[128 * 144];
__device__ __half g_w2[128 * 80];

__device__ __forceinline__ float lrelu(float v) { return v >= 0.f ? v : NS * v; }

__device__ __forceinline__ void atomicMaxF(float* addr, float v) {
    if (v >= 0.f) atomicMax((int*)addr, __float_as_int(v));
    else          atomicMin((unsigned int*)addr, __float_as_uint(v));
}

__device__ __forceinline__ uint32_t smem_u32(const void* p) {
    uint32_t a;
    asm("{ .reg .u64 t; cvta.to.shared.u64 t, %1; cvt.u32.u64 %0, t; }" : "=r"(a) : "l"(p));
    return a;
}
__device__ __forceinline__ void cp16(void* smem, const void* gmem) {
    asm volatile("cp.async.cg.shared.global [%0], [%1], 16;"
                 :: "r"(smem_u32(smem)), "l"(gmem) : "memory");
}
#define CP_COMMIT() asm volatile("cp.async.commit_group;" ::: "memory")
#define CP_WAIT(n)  asm volatile("cp.async.wait_group %0;" :: "n"(n) : "memory")

// ---------------- hist (side stream) -------------------------------------------
#define HIST_BLKS 782
__global__ void k_hist(const int* __restrict__ ei) {
    int i = blockIdx.x * blockDim.x + threadIdx.x;
    if (i >= NE / 4) return;
    int4 d4 = ((const int4*)(ei + NE))[i];
    atomicAdd(&g_deg[d4.x], 1);
    atomicAdd(&g_deg[d4.y], 1);
    atomicAdd(&g_deg[d4.z], 1);
    atomicAdd(&g_deg[d4.w], 1);
}

// ---------------- convw + reset (main stream) ---------------------------------
#define CONV_BLKS 112
__global__ void k_convw(const float* __restrict__ W1, const float* __restrict__ W2,
                        const float* __restrict__ as1, const float* __restrict__ ad1,
                        const float* __restrict__ as2, const float* __restrict__ ad2) {
    int b = blockIdx.x, t = threadIdx.x;
    if (b == CONV_BLKS) {
        if (t < NBLK) g_blkst[t] = 0u;
        if (t == 0) {
            g_off[NN] = ET;
            g_mx1[0] = -3.4e38f; g_mx1[1] = -3.4e38f;
            g_mx1[2] = -3.4e38f; g_mx1[3] = -3.4e38f;
            g_mx2 = -3.4e38f;
        }
        return;
    }
    int s = b * 256 + t;
    float val; int dsth, dstl;
    if (s < 16384) {
        int k = s >> 7, n = s & 127;
        val = W1[k * 128 + n];
        dsth = k * 144 + n; dstl = 1;
    } else if (s < 17408) {
        int i = s - 16384;
        int k = i >> 3, c = i & 7, h = c >> 1;
        const float* a = (c & 1) ? ad1 : as1;
        float sum = 0.f;
#pragma unroll
        for (int f = 0; f < 32; f++) sum += W1[k * 128 + h * 32 + f] * a[h * 32 + f];
        val = sum; dsth = k * 144 + 128 + c; dstl = 1;
    } else if (s < 18432) {
        int i = s - 17408;
        int k = i >> 3, c = i & 7;
        val = 0.f; dsth = k * 144 + 136 + c; dstl = 1;
    } else if (s < 26624) {
        int i = s - 18432;
        int k = i >> 6, n = i & 63;
        val = W2[k * 64 + n];
        dsth = k * 80 + n; dstl = 2;
    } else if (s < 26880) {
        int i = s - 26624;
        int k = i >> 1, c = i & 1;
        const float* a = c ? ad2 : as2;
        float sum = 0.f;
#pragma unroll
        for (int f = 0; f < 64; f++) sum += W2[k * 64 + f] * a[f];
        val = sum; dsth = k * 80 + 64 + c; dstl = 2;
    } else if (s < 28672) {
        int i = s - 26880;
        int k = i / 14, c = i % 14;
        val = 0.f; dsth = k * 80 + 66 + c; dstl = 2;
    } else return;
    __half hv = __float2half_rn(val);
    if (dstl == 1) g_w1[dsth] = hv;
    else           g_w2[dsth] = hv;
}

// ---------------- single-pass scan with decoupled lookback --------------------
__global__ void k_scan() {
    __shared__ int sh[256];
    __shared__ int s_excl;
    int t = threadIdx.x, b = blockIdx.x;
    int i = b * 256 + t;
    int v = (i < NN) ? g_deg[i] + 1 : 0;
    sh[t] = v;
    __syncthreads();
#pragma unroll
    for (int o = 1; o < 256; o <<= 1) {
        int tv = (t >= o) ? sh[t - o] : 0;
        __syncthreads();
        sh[t] += tv;
        __syncthreads();
    }
    int incl = sh[t];
    int total = sh[255];

    if (t == 0) {
        if (b == 0) {
            atomicExch(&g_blkst[0], ((unsigned)total << 2) | 2u);
            s_excl = 0;
        } else {
            atomicExch(&g_blkst[b], ((unsigned)total << 2) | 1u);
            int run = 0;
            for (int p = b - 1; p >= 0; p--) {
                unsigned st;
                do { st = atomicAdd(&g_blkst[p], 0u); } while ((st & 3u) == 0u);
                run += (int)(st >> 2);
                if ((st & 3u) == 2u) break;
            }
            s_excl = run;
            atomicExch(&g_blkst[b], ((unsigned)(run + total) << 2) | 2u);
        }
    }
    __syncthreads();
    if (i < NN) {
        int off = s_excl + incl - v;
        g_off[i] = off;
        g_srcidx[off] = i;
        g_cur[i] = off + 1;
        g_deg[i] = 0;
    }
}

__global__ void k_fill(const int* __restrict__ ei) {
    int i = blockIdx.x * blockDim.x + threadIdx.x;
    if (i >= NE / 4) return;
    int4 s4 = ((const int4*)ei)[i];
    int4 d4 = ((const int4*)(ei + NE))[i];
    int p;
    p = atomicAdd(&g_cur[d4.x], 1); g_srcidx[p] = s4.x;
    p = atomicAdd(&g_cur[d4.y], 1); g_srcidx[p] = s4.y;
    p = atomicAdd(&g_cur[d4.z], 1); g_srcidx[p] = s4.z;
    p = atomicAdd(&g_cur[d4.w], 1); g_srcidx[p] = s4.w;
}

// ---------------- GEMM1: [h1 | as1 | ad1] = x @ [W1 | W1@P] -------------------
// X and W as independent cp.async groups into SEPARATE smem regions:
// conversion overlaps W's in-flight load.
#define LDA 136
#define LDW1 152
#define ST1 148
__global__ __launch_bounds__(256)
void k_gemm1_mma(const float* __restrict__ X) {
    extern __shared__ char raw[];
    __half* sAh = (__half*)raw;
    __half* sAl = sAh + 64 * LDA;
    __half* sW  = (__half*)(raw + 4 * 64 * LDA);                 // 34816
    float*  sX  = (float*)(raw + 4 * 64 * LDA + 2 * 128 * LDW1); // 73728
    float* stage = (float*)raw;
    int tid = threadIdx.x;
    int row0 = blockIdx.x * 64;

    // group A: X fp32 tile -> sX
#pragma unroll
    for (int ii = 0; ii < 8; ii++) {
        int i = tid + ii * 256;
        int r = i >> 5, c4 = i & 31;
        if (row0 + r < NN)
            cp16(sX + r * 128 + 4 * c4, (const float4*)X + (size_t)(row0 + r) * 32 + c4);
        else
            *(float4*)(sX + r * 128 + 4 * c4) = make_float4(0.f, 0.f, 0.f, 0.f);
    }
    CP_COMMIT();
    // group B: W fp16 -> sW (in flight during conversion)
    for (int i = tid; i < 2304; i += 256) {
        int k = i / 18, j = i % 18;
        cp16(sW + k * LDW1 + 8 * j, (const uint4*)g_w1 + i);
    }
    CP_COMMIT();

    CP_WAIT(1);            // X landed (W may still be pending)
    __syncthreads();
#pragma unroll
    for (int ii = 0; ii < 8; ii++) {
        int i = tid + ii * 256;
        int r = i >> 5, c4 = i & 31;
        float4 v = *(const float4*)(sX + r * 128 + 4 * c4);
        __half2 h0 = __floats2half2_rn(v.x, v.y);
        __half2 h1 = __floats2half2_rn(v.z, v.w);
        float2 f0 = __half22float2(h0), f1 = __half22float2(h1);
        __half2 l0 = __floats2half2_rn(v.x - f0.x, v.y - f0.y);
        __half2 l1 = __floats2half2_rn(v.z - f1.x, v.w - f1.y);
        uint2 uh, ul;
        uh.x = *(uint32_t*)&h0; uh.y = *(uint32_t*)&h1;
        ul.x = *(uint32_t*)&l0; ul.y = *(uint32_t*)&l1;
        *(uint2*)(sAh + r * LDA + 4 * c4) = uh;
        *(uint2*)(sAl + r * LDA + 4 * c4) = ul;
    }
    CP_WAIT(0);            // W landed
    __syncthreads();

    int w = tid >> 5, wr = w >> 1, wc = w & 1;
    const int nf = wc ? 4 : 5;
    const int col0 = wc * 80;

    wmma::fragment<wmma::accumulator, 16, 16, 16, float> c[5];
#pragma unroll
    for (int j = 0; j < 5; j++) wmma::fill_fragment(c[j], 0.f);

    for (int kk = 0; kk < 128; kk += 16) {
        wmma::fragment<wmma::matrix_a, 16, 16, 16, __half, wmma::row_major> ah, al;
        wmma::load_matrix_sync(ah, sAh + (wr * 16) * LDA + kk, LDA);
        wmma::load_matrix_sync(al, sAl + (wr * 16) * LDA + kk, LDA);
#pragma unroll
        for (int j = 0; j < 5; j++) {
            if (j >= nf) break;
            wmma::fragment<wmma::matrix_b, 16, 16, 16, __half, wmma::row_major> bh;
            wmma::load_matrix_sync(bh, sW + kk * LDW1 + col0 + j * 16, LDW1);
            wmma::mma_sync(c[j], ah, bh, c[j]);
            wmma::mma_sync(c[j], al, bh, c[j]);
        }
    }
    __syncthreads();
#pragma unroll
    for (int j = 0; j < 5; j++) {
        if (j >= nf) break;
        wmma::store_matrix_sync(stage + (wr * 16) * ST1 + col0 + j * 16,
                                c[j], ST1, wmma::mem_row_major);
    }
    __syncthreads();

    {
        int r = tid >> 2, q = tid & 3;
        int row = row0 + r;
        if (row < NN) {
            const float* sp = stage + r * ST1 + 32 * q;
            uint4* dp = (uint4*)(g_h1h + (size_t)row * 128 + 32 * q);
#pragma unroll
            for (int u = 0; u < 4; u++) {
                float4 a = *(const float4*)(sp + 8 * u);
                float4 b = *(const float4*)(sp + 8 * u + 4);
                __half2 h0 = __floats2half2_rn(a.x, a.y);
                __half2 h1 = __floats2half2_rn(a.z, a.w);
                __half2 h2 = __floats2half2_rn(b.x, b.y);
                __half2 h3 = __floats2half2_rn(b.z, b.w);
                uint4 uu;
                uu.x = *(uint32_t*)&h0; uu.y = *(uint32_t*)&h1;
                uu.z = *(uint32_t*)&h2; uu.w = *(uint32_t*)&h3;
                dp[u] = uu;
            }
        }
    }
    if (tid < 64) {
        int row = row0 + tid;
        const float* sp = stage + tid * ST1 + 128;
        float ps[4];
#pragma unroll
        for (int h = 0; h < 4; h++) {
            float a_ = sp[2 * h], d_ = sp[2 * h + 1];
            if (row < NN) {
                g_as1[row * 4 + h] = a_;
                g_ad1[row * 4 + h] = d_;
                ps[h] = a_;
            } else ps[h] = -3.4e38f;
        }
#pragma unroll
        for (int h = 0; h < 4; h++) {
#pragma unroll
            for (int o = 16; o >= 1; o >>= 1)
                ps[h] = fmaxf(ps[h], __shfl_xor_sync(0xffffffffu, ps[h], o));
        }
        if ((tid & 31) == 0) {
#pragma unroll
            for (int h = 0; h < 4; h++) atomicMaxF(&g_mx1[h], ps[h]);
        }
    }
}

// ---------------- GEMM2: [h2 | as2 | ad2] = o1 @ [W2 | W2@P2] -----------------
#define LDW2 88
#define ST2 84
__global__ __launch_bounds__(256)
void k_gemm2_mma() {
    extern __shared__ char raw[];
    __half* sAh = (__half*)raw;
    __half* sAl = sAh + 64 * LDA;
    __half* sW  = (__half*)(raw + 4 * 64 * LDA);
    float* stage = (float*)raw;
    int tid = threadIdx.x;
    int row0 = blockIdx.x * 64;

#pragma unroll
    for (int ii = 0; ii < 4; ii++) {
        int i = tid + ii * 256;
        int r = i >> 4, c = i & 15;
        if (row0 + r < NN) {
            cp16(sAh + r * LDA + 8 * c, (const uint4*)g_o1h + (size_t)(row0 + r) * 16 + c);
            cp16(sAl + r * LDA + 8 * c, (const uint4*)g_o1l + (size_t)(row0 + r) * 16 + c);
        } else {
            *(uint4*)(sAh + r * LDA + 8 * c) = make_uint4(0, 0, 0, 0);
            *(uint4*)(sAl + r * LDA + 8 * c) = make_uint4(0, 0, 0, 0);
        }
    }
    for (int i = tid; i < 1280; i += 256) {
        int k = i / 10, j = i % 10;
        cp16(sW + k * LDW2 + 8 * j, (const uint4*)g_w2 + i);
    }
    CP_COMMIT();
    CP_WAIT(0);
    __syncthreads();

    int w = tid >> 5, wr = w >> 1, wc = w & 1;
    const int nf = wc ? 2 : 3;
    const int col0 = wc * 48;

    wmma::fragment<wmma::accumulator, 16, 16, 16, float> c[3];
#pragma unroll
    for (int j = 0; j < 3; j++) wmma::fill_fragment(c[j], 0.f);

    for (int kk = 0; kk < 128; kk += 16) {
        wmma::fragment<wmma::matrix_a, 16, 16, 16, __half, wmma::row_major> ah, al;
        wmma::load_matrix_sync(ah, sAh + (wr * 16) * LDA + kk, LDA);
        wmma::load_matrix_sync(al, sAl + (wr * 16) * LDA + kk, LDA);
#pragma unroll
        for (int j = 0; j < 3; j++) {
            if (j >= nf) break;
            wmma::fragment<wmma::matrix_b, 16, 16, 16, __half, wmma::row_major> bh;
            wmma::load_matrix_sync(bh, sW + kk * LDW2 + col0 + j * 16, LDW2);
            wmma::mma_sync(c[j], ah, bh, c[j]);
            wmma::mma_sync(c[j], al, bh, c[j]);
        }
    }
    __syncthreads();
#pragma unroll
    for (int j = 0; j < 3; j++) {
        if (j >= nf) break;
        wmma::store_matrix_sync(stage + (wr * 16) * ST2 + col0 + j * 16,
                                c[j], ST2, wmma::mem_row_major);
    }
    __syncthreads();

    {
        int r = tid >> 2, q = tid & 3;
        int row = row0 + r;
        if (row < NN) {
            const float* sp = stage + r * ST2 + 16 * q;
            uint4* dp = (uint4*)(g_h2h + (size_t)row * 64 + 16 * q);
#pragma unroll
            for (int u = 0; u < 2; u++) {
                float4 a = *(const float4*)(sp + 8 * u);
                float4 b = *(const float4*)(sp + 8 * u + 4);
                __half2 h0 = __floats2half2_rn(a.x, a.y);
                __half2 h1 = __floats2half2_rn(a.z, a.w);
                __half2 h2 = __floats2half2_rn(b.x, b.y);
                __half2 h3 = __floats2half2_rn(b.z, b.w);
                uint4 uu;
                uu.x = *(uint32_t*)&h0; uu.y = *(uint32_t*)&h1;
                uu.z = *(uint32_t*)&h2; uu.w = *(uint32_t*)&h3;
                dp[u] = uu;
            }
        }
    }
    if (tid < 64) {
        int row = row0 + tid;
        float ps;
        if (row < NN) {
            ps = stage[tid * ST2 + 64];
            g_as2[row] = ps;
            g_ad2[row] = stage[tid * ST2 + 65];
        } else ps = -3.4e38f;
#pragma unroll
        for (int o = 16; o >= 1; o >>= 1)
            ps = fmaxf(ps, __shfl_xor_sync(0xffffffffu, ps, o));
        if ((tid & 31) == 0) atomicMaxF(&g_mx2, ps);
    }
}

// ---------------- gather1: 2 edges/warp, depth-2 pipeline ---------------------
__global__ __launch_bounds__(256)
void k_gather1(const float* __restrict__ b1) {
    int n = blockIdx.x * 8 + (threadIdx.x >> 5);
    if (n >= NN) return;
    int lane = threadIdx.x & 31;
    int g = lane >> 4, li = lane & 15;
    int head = li >> 2;
    float adh = g_ad1[4 * n + head];
    int beg = g_off[n], end = g_off[n + 1];

    float mh = lrelu(g_mx1[head] + adh);

    float acc[8];
#pragma unroll
    for (int q = 0; q < 8; q++) acc[q] = 0.f;
    float den = 0.f;

    int j0 = beg + g;
    float aA = 0.f, aB = 0.f;
    uint4 uA = make_uint4(0, 0, 0, 0), uB = make_uint4(0, 0, 0, 0);
    if (j0 < end) {
        int s = g_srcidx[j0];
        aA = g_as1[4 * s + head];
        uA = *(const uint4*)(g_h1h + (size_t)s * 128 + 8 * li);
    }
    if (j0 + 2 < end) {
        int s = g_srcidx[j0 + 2];
        aB = g_as1[4 * s + head];
        uB = *(const uint4*)(g_h1h + (size_t)s * 128 + 8 * li);
    }
    for (int j = j0; j < end; j += 2) {
        float aC = 0.f; uint4 uC = make_uint4(0, 0, 0, 0);
        if (j + 4 < end) {
            int s = g_srcidx[j + 4];
            aC = g_as1[4 * s + head];
            uC = *(const uint4*)(g_h1h + (size_t)s * 128 + 8 * li);
        }
        float w = __expf(lrelu(aA + adh) - mh);
        den += w;
        const __half2* hp = (const __half2*)&uA;
#pragma unroll
        for (int q = 0; q < 4; q++) {
            float2 f = __half22float2(hp[q]);
            acc[2 * q] += w * f.x;
            acc[2 * q + 1] += w * f.y;
        }
        aA = aB; uA = uB;
        aB = aC; uB = uC;
    }
    den += __shfl_xor_sync(0xffffffffu, den, 16);
#pragma unroll
    for (int q = 0; q < 8; q++) acc[q] += __shfl_xor_sync(0xffffffffu, acc[q], 16);

    if (g == 0) {
        float inv = 1.f / (den + 1e-16f);
        float4 b0 = *(const float4*)(b1 + 8 * li);
        float4 b4 = *(const float4*)(b1 + 8 * li + 4);
        float v[8];
        v[0] = fmaxf(acc[0] * inv + b0.x, 0.f); v[1] = fmaxf(acc[1] * inv + b0.y, 0.f);
        v[2] = fmaxf(acc[2] * inv + b0.z, 0.f); v[3] = fmaxf(acc[3] * inv + b0.w, 0.f);
        v[4] = fmaxf(acc[4] * inv + b4.x, 0.f); v[5] = fmaxf(acc[5] * inv + b4.y, 0.f);
        v[6] = fmaxf(acc[6] * inv + b4.z, 0.f); v[7] = fmaxf(acc[7] * inv + b4.w, 0.f);
        uint4 uh, ul;
        uint32_t* uhp = (uint32_t*)&uh;
        uint32_t* ulp = (uint32_t*)&ul;
#pragma unroll
        for (int q = 0; q < 4; q++) {
            __half2 h = __floats2half2_rn(v[2 * q], v[2 * q + 1]);
            float2 f = __half22float2(h);
            __half2 l = __floats2half2_rn(v[2 * q] - f.x, v[2 * q + 1] - f.y);
            uhp[q] = *(uint32_t*)&h;
            ulp[q] = *(uint32_t*)&l;
        }
        *(uint4*)(g_o1h + (size_t)n * 128 + 8 * li) = uh;
        *(uint4*)(g_o1l + (size_t)n * 128 + 8 * li) = ul;
    }
}

// ---------------- gather2: 4 edges/warp, depth-2 pipeline ---------------------
__global__ __launch_bounds__(256)
void k_gather2(const float* __restrict__ b2, float* __restrict__ out) {
    int n = blockIdx.x * 8 + (threadIdx.x >> 5);
    if (n >= NN) return;
    int lane = threadIdx.x & 31;
    int g = lane >> 3, li = lane & 7;
    float adh = g_ad2[n];
    int beg = g_off[n], end = g_off[n + 1];

    float mh = lrelu(g_mx2 + adh);

    float acc[8];
#pragma unroll
    for (int q = 0; q < 8; q++) acc[q] = 0.f;
    float den = 0.f;

    int j0 = beg + g;
    float aA = 0.f, aB = 0.f;
    uint4 uA = make_uint4(0, 0, 0, 0), uB = make_uint4(0, 0, 0, 0);
    if (j0 < end) {
        int s = g_srcidx[j0];
        aA = g_as2[s];
        uA = *(const uint4*)(g_h2h + (size_t)s * 64 + 8 * li);
    }
    if (j0 + 4 < end) {
        int s = g_srcidx[j0 + 4];
        aB = g_as2[s];
        uB = *(const uint4*)(g_h2h + (size_t)s * 64 + 8 * li);
    }
    for (int j = j0; j < end; j += 4) {
        float aC = 0.f; uint4 uC = make_uint4(0, 0, 0, 0);
        if (j + 8 < end) {
            int s = g_srcidx[j + 8];
            aC = g_as2[s];
            uC = *(const uint4*)(g_h2h + (size_t)s * 64 + 8 * li);
        }
        float w = __expf(lrelu(aA + adh) - mh);
        den += w;
        const __half2* hp = (const __half2*)&uA;
#pragma unroll
        for (int q = 0; q < 4; q++) {
            float2 f = __half22float2(hp[q]);
            acc[2 * q] += w * f.x;
            acc[2 * q + 1] += w * f.y;
        }
        aA = aB; uA = uB;
        aB = aC; uB = uC;
    }
    den += __shfl_xor_sync(0xffffffffu, den, 8);
    den += __shfl_xor_sync(0xffffffffu, den, 16);
#pragma unroll
    for (int q = 0; q < 8; q++) {
        acc[q] += __shfl_xor_sync(0xffffffffu, acc[q], 8);
        acc[q] += __shfl_xor_sync(0xffffffffu, acc[q], 16);
    }

    if (g == 0) {
        float inv = 1.f / (den + 1e-16f);
        float4 b0 = *(const float4*)(b2 + 8 * li);
        float4 b4 = *(const float4*)(b2 + 8 * li + 4);
        float* op = out + (size_t)n * 64 + 8 * li;
        *(float4*)op = make_float4(acc[0] * inv + b0.x, acc[1] * inv + b0.y,
                                   acc[2] * inv + b0.z, acc[3] * inv + b0.w);
        *(float4*)(op + 4) = make_float4(acc[4] * inv + b4.x, acc[5] * inv + b4.y,
                                         acc[6] * inv + b4.z, acc[7] * inv + b4.w);
    }
}

// ---------------- launch ------------------------------------------------------
extern "C" void kernel_launch(void* const* d_in, const int* in_sizes, int n_in,
                              void* d_out, int out_size) {
    const float* x   = (const float*)d_in[0];
    const int*   ei  = (const int*)d_in[1];
    const float* W1  = (const float*)d_in[2];
    const float* as1 = (const float*)d_in[3];
    const float* ad1 = (const float*)d_in[4];
    const float* b1  = (const float*)d_in[5];
    const float* W2  = (const float*)d_in[6];
    const float* as2 = (const float*)d_in[7];
    const float* ad2 = (const float*)d_in[8];
    const float* b2  = (const float*)d_in[9];
    float* out = (float*)d_out;

    const int smem1 = 4 * 64 * LDA + 2 * 128 * LDW1 + 64 * 128 * 4;  // 106496
    const int smem2 = 4 * 64 * LDA + 2 * 128 * LDW2;                 // 57344
    static cudaStream_t s_side = nullptr;
    static cudaEvent_t ev0 = nullptr, evC = nullptr, evS = nullptr;
    if (!s_side) {
        cudaFuncSetAttribute(k_gemm1_mma, cudaFuncAttributeMaxDynamicSharedMemorySize, smem1);
        cudaFuncSetAttribute(k_gemm2_mma, cudaFuncAttributeMaxDynamicSharedMemorySize, smem2);
        cudaStreamCreateWithFlags(&s_side, cudaStreamNonBlocking);
        cudaEventCreateWithFlags(&ev0, cudaEventDisableTiming);
        cudaEventCreateWithFlags(&evC, cudaEventDisableTiming);
        cudaEventCreateWithFlags(&evS, cudaEventDisableTiming);
    }

    // fork at t=0: hist on side (needs only ei)
    cudaEventRecord(ev0, 0);
    cudaStreamWaitEvent(s_side, ev0, 0);
    k_hist<<<HIST_BLKS, 256, 0, s_side>>>(ei);

    // main: convw + reset
    k_convw<<<CONV_BLKS + 1, 256>>>(W1, W2, as1, ad1, as2, ad2);
    cudaEventRecord(evC, 0);

    // side: scan (hist + reset), fill
    cudaStreamWaitEvent(s_side, evC, 0);
    k_scan<<<NBLK, 256, 0, s_side>>>();
    k_fill<<<(NE / 4 + 255) / 256, 256, 0, s_side>>>(ei);
    cudaEventRecord(evS, s_side);

    // main: gemm1 concurrent with side CSR chain
    k_gemm1_mma<<<NP / 64, 256, smem1>>>(x);

    // join: gather1 needs gemm1 (main) + fill (side)
    cudaStreamWaitEvent(0, evS, 0);
    k_gather1<<<(NN + 7) / 8, 256>>>(b1);

    // layer 2 (serial chain)
    k_gemm2_mma<<<NP / 64, 256, smem2>>>();
    k_gather2<<<(NN + 7) / 8, 256>>>(b2, out);
}